// round 15
// baseline (speedup 1.0000x reference)
#include <cuda_runtime.h>
#include <cuda.h>
#include <cuda_bf16.h>

// UmbralCone: hyperbolic cone distance.
//  weight: f32 [100000, 32] (d_in[0]);  inputs: i32 [16384, 50] (d_in[1])
//  out: f32 [16384, 49]
//
// TMA gather4 chassis (R13: L2 22.8%, occ 86%) with the ALU stripped back:
//  - parents copied to linear stride-9 scratch in 2a -> pv reads use
//    immediate offsets; diagonal rotation only on cv reads.
//  - all-int32 indexing; out index = row0*49 + tid  (since j = tid - r*49,
//    (row0+r)*49 + j == row0*49 + tid).  [R14 bug: wrote tid - r.]
// Fallback to the proven cp.async kernel if tensormap creation fails.

#define RPB   2
#define KTOT  50
#define NCH   49
#define NROWS (RPB * KTOT)   // 100
#define RSTR  9              // fallback: float4 stride per row

__device__ __forceinline__ void cp16(const float4* dst_smem, const float4* src_gmem) {
    unsigned dst = (unsigned)__cvta_generic_to_shared(dst_smem);
    asm volatile("cp.async.cg.shared.global [%0], [%1], 16;\n"
                 :: "r"(dst), "l"(src_gmem));
}

// a = (inv_np, sin_beta, cos_beta, hp); b = (2*scale, nps2, 2/(1-nps2), 0)
__device__ __forceinline__ void parent_scalars(float np2, float4& a, float4& b) {
    const float SINH_R = 0.10016675001984403f;   // sinh(0.1)
    const float COSH_R = 1.0050041680558035f;    // cosh(0.1)
    const float EK     = 1.0100501670841680f;    // exp(0.01)
    float np      = sqrtf(np2);
    float inv_np  = __fdividef(1.0f, np);
    float sin_beta = SINH_R * 0.5f * (1.0f - np2) * inv_np;
    float cos_beta = sqrtf(fmaxf(1.0f - sin_beta * sin_beta, 0.0f));
    float zp = fmaxf(COSH_R * __fdividef(1.0f - np2, 1.0f + np2), 1.0f + 1e-7f);
    float hp = __logf(zp + sqrtf(zp * zp - 1.0f));   // arcosh
    float tmp   = __fdividef(1.0f + np, 1.0f - np);
    float ektmp = EK * tmp;
    float scale = __fdividef(ektmp - 1.0f, (ektmp + 1.0f) * np);
    float nps2  = scale * scale * np2;
    float w2    = __fdividef(2.0f, 1.0f - nps2);
    a = make_float4(inv_np, sin_beta, cos_beta, hp);
    b = make_float4(2.0f * scale, nps2, w2, 0.0f);
}

__device__ __forceinline__ float pair_tail(float nc2, float dot, float4 a, float4 b) {
    float inv_nc = rsqrtf(nc2);
    float nc     = nc2 * inv_nc;
    float ca = dot * a.x * inv_nc;
    ca = fminf(fmaxf(ca, -1.0f + 1e-7f), 1.0f - 1e-7f);
    float sa = sqrtf(1.0f - ca * ca);            // sin(alpha)
    float sin_theta = sa * a.z - ca * a.y;       // sin(alpha - beta)
    float temp = 2.0f * nc * sin_theta;
    float omn     = 1.0f - nc2;
    float inv_omn = __fdividef(1.0f, omn);
    float hc = (1.0f + nc2) * rsqrtf(fmaf(omn, omn, temp * temp));
    bool  up = (a.w - hc) > 0.0f;                // altitude > 0
    float diff2 = fmaf(-b.x, dot, nc2 + b.y);            // |c - s*p|^2
    float z = fmaf(b.z * diff2, inv_omn, 1.0f);          // arcosh arg
    float x = temp * inv_omn;                            // asinh arg
    float A   = up ? fmaxf(z, 1.0f + 1e-7f) : fabsf(x);
    float sgn = up ? -1.0f : 1.0f;
    float val = __logf(A + sqrtf(fmaf(A, A, sgn)));
    return up ? val : copysignf(val, x) + 0.1f;          // +RADIUS
}

// ---------------- TMA gather4 kernel ----------------
__global__ __launch_bounds__(128, 14)
void umbral_tma_kernel(const __grid_constant__ CUtensorMap tmap,
                       const int* __restrict__ inputs,
                       float* __restrict__ out,
                       int B) {
    __shared__ __align__(128) float4 s4[NROWS * 8];   // rows at 128B stride
    __shared__ __align__(16) float4 spar[2 * 9];      // linear parent rows
    __shared__ __align__(16) float4 srow[RPB * 2];
    __shared__ __align__(8) unsigned long long mbar_s;

    const int tid   = threadIdx.x;
    const int row0  = blockIdx.x * RPB;
    const int gbase = row0 * KTOT;                    // fits int32
    const bool full = (row0 + RPB <= B);

    const unsigned mb = (unsigned)__cvta_generic_to_shared(&mbar_s);
    const unsigned sb = (unsigned)__cvta_generic_to_shared(s4);

    if (tid == 0)
        asm volatile("mbarrier.init.shared.b64 [%0], 1;" :: "r"(mb) : "memory");
    __syncthreads();

    if (tid < 32) {
        if (tid == 0)
            asm volatile("mbarrier.arrive.expect_tx.shared.b64 _, [%0], %1;"
                         :: "r"(mb), "r"(NROWS * 128) : "memory");
        __syncwarp();
        if (tid < NROWS / 4) {
            const int g = tid * 4;
            int i0, i1, i2, i3;
            if (full) {
                const int2* p = (const int2*)(inputs + gbase + g);  // 8B aligned
                int2 v0 = p[0], v1 = p[1];
                i0 = v0.x; i1 = v0.y; i2 = v1.x; i3 = v1.y;
            } else {
                const int lim = (B - row0) * KTOT;
                i0 = (g + 0 < lim) ? inputs[gbase + g + 0] : 0;
                i1 = (g + 1 < lim) ? inputs[gbase + g + 1] : 0;
                i2 = (g + 2 < lim) ? inputs[gbase + g + 2] : 0;
                i3 = (g + 3 < lim) ? inputs[gbase + g + 3] : 0;
            }
            asm volatile(
                "cp.async.bulk.tensor.2d.shared::cta.global.tile::gather4"
                ".mbarrier::complete_tx::bytes [%0], [%1, {%2, %3, %4, %5, %6}], [%7];"
                :: "r"(sb + g * 128), "l"(&tmap), "r"(0),
                   "r"(i0), "r"(i1), "r"(i2), "r"(i3), "r"(mb)
                : "memory");
        }
    }

    // Wait for the gather (parity 0).
    {
        unsigned done;
        asm volatile(
            "{\n\t.reg .pred p;\n\t"
            "mbarrier.try_wait.parity.acquire.cta.shared::cta.b64 p, [%1], 0;\n\t"
            "selp.b32 %0, 1, 0, p;\n\t}"
            : "=r"(done) : "r"(mb) : "memory");
        if (!done) {
            asm volatile(
                "{\n\t.reg .pred P1;\n"
                "WL_%=:\n\t"
                "mbarrier.try_wait.parity.acquire.cta.shared::cta.b64 P1, [%0], 0, 0x989680;\n\t"
                "@P1 bra.uni WD_%=;\n\t"
                "bra.uni WL_%=;\n"
                "WD_%=:\n\t}"
                :: "r"(mb) : "memory");
        }
    }

    // ---------- Phase 2a: parent scalars + copy parent rows to linear scratch ----------
    if (tid < RPB && (full || tid < B - row0)) {
        const float4* pb = &s4[(tid * KTOT) * 8];     // parent row, natural order
        float np2 = 0.f;
        #pragma unroll
        for (int i = 0; i < 8; i++) {
            float4 v = pb[i];                         // 1-2 active lanes: no conflict
            spar[tid * 9 + i] = v;
            np2 = fmaf(v.x, v.x, fmaf(v.y, v.y, fmaf(v.z, v.z, fmaf(v.w, v.w, np2))));
        }
        float4 a, b;
        parent_scalars(np2, a, b);
        srow[tid * 2 + 0] = a;
        srow[tid * 2 + 1] = b;
    }
    __syncthreads();

    // ---------- Phase 2b: one thread per (row, child) pair ----------
    if (tid < RPB * NCH) {
        const int r = (tid >= NCH);
        if (full || row0 + r < B) {
            const int c = r + 1 + tid - r * NCH + r * (KTOT - 1);  // r*KTOT + 1 + j
            const int m = c & 7;
            const float4* cb = &s4[c * 8];
            const float4* pv = &spar[r * 9];          // immediate offsets

            float nc2 = 0.f, dot = 0.f;
            #pragma unroll
            for (int i = 0; i < 8; i++) {
                const int o = (i + m) & 7;            // slot o: conflict-free
                float4 cv = cb[o];
                float4 p  = pv[o];                    // broadcast (same addr per r)
                nc2 = fmaf(cv.x, cv.x, nc2); nc2 = fmaf(cv.y, cv.y, nc2);
                nc2 = fmaf(cv.z, cv.z, nc2); nc2 = fmaf(cv.w, cv.w, nc2);
                dot = fmaf(p.x, cv.x, dot);  dot = fmaf(p.y, cv.y, dot);
                dot = fmaf(p.z, cv.z, dot);  dot = fmaf(p.w, cv.w, dot);
            }
            float dist = pair_tail(nc2, dot, srow[r * 2 + 0], srow[r * 2 + 1]);
            out[row0 * NCH + tid] = dist;             // (row0+r)*49 + j == row0*49 + tid
        }
    }
}

// ---------------- fallback: proven cp.async kernel (~17.1us) ----------------
__global__ __launch_bounds__(128, 14)
void umbral_cone_kernel(const float* __restrict__ weight,
                        const int* __restrict__ inputs,
                        float* __restrict__ out,
                        int B) {
    __shared__ __align__(16) float4 s4[NROWS * RSTR];
    __shared__ __align__(16) float4 srow[RPB * 2];

    const int tid  = threadIdx.x;
    const int row0 = blockIdx.x * RPB;
    const int g0   = tid >> 3;
    const int fi   = tid & 7;
    const int gbase = row0 * KTOT;
    const bool full = (row0 + RPB <= B);

    if (full) {
        int idxv[7];
        #pragma unroll
        for (int u = 0; u < 7; u++) {
            int g = g0 + 16 * u;
            if (u < 6 || g0 < NROWS - 96)
                idxv[u] = inputs[gbase + g];
        }
        #pragma unroll
        for (int u = 0; u < 7; u++) {
            int g = g0 + 16 * u;
            if (u < 6 || g0 < NROWS - 96)
                cp16(&s4[g * RSTR + fi], (const float4*)(weight + idxv[u] * 32) + fi);
        }
    } else {
        const int lim = (B - row0) * KTOT;
        #pragma unroll
        for (int u = 0; u < 7; u++) {
            int g = g0 + 16 * u;
            if (g < lim && g < NROWS) {
                int idx = inputs[gbase + g];
                cp16(&s4[g * RSTR + fi], (const float4*)(weight + idx * 32) + fi);
            }
        }
    }
    asm volatile("cp.async.commit_group;\n");
    asm volatile("cp.async.wait_group 0;\n" ::: "memory");
    __syncthreads();

    if (tid < RPB && (full || tid < B - row0)) {
        const float4* pb = &s4[(tid * KTOT) * RSTR];
        float np2 = 0.f;
        #pragma unroll
        for (int i = 0; i < 8; i++) {
            float4 v = pb[i];
            np2 = fmaf(v.x, v.x, fmaf(v.y, v.y, fmaf(v.z, v.z, fmaf(v.w, v.w, np2))));
        }
        float4 a, b;
        parent_scalars(np2, a, b);
        srow[tid * 2 + 0] = a;
        srow[tid * 2 + 1] = b;
    }
    __syncthreads();

    if (tid < RPB * NCH) {
        const int r = (tid >= NCH);
        const int j = tid - r * NCH;
        if (full || row0 + r < B) {
            const float4* pb = &s4[(r * KTOT) * RSTR];
            const float4* cb = &s4[(r * KTOT + 1 + j) * RSTR];
            float nc2 = 0.f, dot = 0.f;
            #pragma unroll
            for (int i = 0; i < 8; i++) {
                float4 pv = pb[i];
                float4 cv = cb[i];
                nc2 = fmaf(cv.x, cv.x, nc2); nc2 = fmaf(cv.y, cv.y, nc2);
                nc2 = fmaf(cv.z, cv.z, nc2); nc2 = fmaf(cv.w, cv.w, nc2);
                dot = fmaf(pv.x, cv.x, dot); dot = fmaf(pv.y, cv.y, dot);
                dot = fmaf(pv.z, cv.z, dot); dot = fmaf(pv.w, cv.w, dot);
            }
            float dist = pair_tail(nc2, dot, srow[r * 2 + 0], srow[r * 2 + 1]);
            out[row0 * NCH + tid] = dist;             // (row0+r)*49 + j
        }
    }
}

// ---------------- launch ----------------
typedef CUresult (*PFN_encodeTiled)(
    CUtensorMap*, CUtensorMapDataType, cuuint32_t, void*,
    const cuuint64_t*, const cuuint64_t*, const cuuint32_t*, const cuuint32_t*,
    CUtensorMapInterleave, CUtensorMapSwizzle, CUtensorMapL2promotion,
    CUtensorMapFloatOOBfill);

extern "C" void kernel_launch(void* const* d_in, const int* in_sizes, int n_in,
                              void* d_out, int out_size) {
    const float* weight = (const float*)d_in[0];
    const int*   inputs = (const int*)d_in[1];
    float*       out    = (float*)d_out;

    int B = in_sizes[1] / KTOT;          // 16384
    int grid = (B + RPB - 1) / RPB;      // 8192
    long long nrows_tbl = in_sizes[0] / 32;

    bool use_tma = false;
    CUtensorMap tmap;
    void* fn = nullptr;
    cudaDriverEntryPointQueryResult qr;
    if (cudaGetDriverEntryPoint("cuTensorMapEncodeTiled", &fn,
                                cudaEnableDefault, &qr) == cudaSuccess && fn) {
        cuuint64_t dims[2]    = {32, (cuuint64_t)nrows_tbl};
        cuuint64_t strides[1] = {128};
        cuuint32_t box[2]     = {32, 1};
        cuuint32_t es[2]      = {1, 1};
        CUresult r = ((PFN_encodeTiled)fn)(
            &tmap, CU_TENSOR_MAP_DATA_TYPE_FLOAT32, 2, (void*)weight,
            dims, strides, box, es,
            CU_TENSOR_MAP_INTERLEAVE_NONE, CU_TENSOR_MAP_SWIZZLE_NONE,
            CU_TENSOR_MAP_L2_PROMOTION_L2_128B, CU_TENSOR_MAP_FLOAT_OOB_FILL_NONE);
        use_tma = (r == CUDA_SUCCESS);
    }

    if (use_tma)
        umbral_tma_kernel<<<grid, 128>>>(tmap, inputs, out, B);
    else
        umbral_cone_kernel<<<grid, 128>>>(weight, inputs, out, B);
}

// round 16
// speedup vs baseline: 1.2557x; 1.2557x over previous
#include <cuda_runtime.h>
#include <cuda_bf16.h>

// UmbralCone: hyperbolic cone distance.  (final consolidated kernel)
//  weight: f32 [100000, 32] (d_in[0]);  inputs: i32 [16384, 50] (d_in[1])
//  out: f32 [16384, 49]
//
// Block of 256 threads handles RPB=5 batch rows (best-measured config, R3):
//  Phase 1: guarded-unroll index preload + cp.async gather of 250 weight
//           rows (128B) into padded row-major SMEM (stride 9 float4 = 144B:
//           conflict-free STS.128 + LDS.128, immediate-offset loads).
//  Phase 2a: 5 threads compute per-row parent scalars (transcendental hoist).
//  Phase 2b: one thread per (row, child) pair (245 of 256): scalar-fmaf
//           dot/norm from SMEM + merged log(A+sqrt(A*A+s)) tail.
//  out index: (row0+r)*49 + j == row0*49 + tid.

#define RPB   5
#define KTOT  50
#define NCH   49
#define NROWS (RPB * KTOT)   // 250
#define RSTR  9              // float4 stride per row (144B)

__device__ __forceinline__ void cp16(const float4* dst_smem, const float4* src_gmem) {
    unsigned dst = (unsigned)__cvta_generic_to_shared(dst_smem);
    asm volatile("cp.async.cg.shared.global [%0], [%1], 16;\n"
                 :: "r"(dst), "l"(src_gmem));
}

// a = (inv_np, sin_beta, cos_beta, hp); b = (2*scale, nps2, 2/(1-nps2), 0)
__device__ __forceinline__ void parent_scalars(float np2, float4& a, float4& b) {
    const float SINH_R = 0.10016675001984403f;   // sinh(0.1)
    const float COSH_R = 1.0050041680558035f;    // cosh(0.1)
    const float EK     = 1.0100501670841680f;    // exp(0.01)
    float np      = sqrtf(np2);
    float inv_np  = __fdividef(1.0f, np);
    float sin_beta = SINH_R * 0.5f * (1.0f - np2) * inv_np;
    float cos_beta = sqrtf(fmaxf(1.0f - sin_beta * sin_beta, 0.0f));
    float zp = fmaxf(COSH_R * __fdividef(1.0f - np2, 1.0f + np2), 1.0f + 1e-7f);
    float hp = __logf(zp + sqrtf(zp * zp - 1.0f));   // arcosh
    float tmp   = __fdividef(1.0f + np, 1.0f - np);
    float ektmp = EK * tmp;
    float scale = __fdividef(ektmp - 1.0f, (ektmp + 1.0f) * np);
    float nps2  = scale * scale * np2;
    float w2    = __fdividef(2.0f, 1.0f - nps2);
    a = make_float4(inv_np, sin_beta, cos_beta, hp);
    b = make_float4(2.0f * scale, nps2, w2, 0.0f);
}

__device__ __forceinline__ float pair_tail(float nc2, float dot, float4 a, float4 b) {
    float inv_nc = rsqrtf(nc2);
    float nc     = nc2 * inv_nc;
    float ca = dot * a.x * inv_nc;
    ca = fminf(fmaxf(ca, -1.0f + 1e-7f), 1.0f - 1e-7f);
    float sa = sqrtf(1.0f - ca * ca);            // sin(alpha)
    float sin_theta = sa * a.z - ca * a.y;       // sin(alpha - beta)
    float temp = 2.0f * nc * sin_theta;
    float omn     = 1.0f - nc2;
    float inv_omn = __fdividef(1.0f, omn);
    float hc = (1.0f + nc2) * rsqrtf(fmaf(omn, omn, temp * temp));
    bool  up = (a.w - hc) > 0.0f;                // altitude > 0
    // Merged arcosh/asinh: both are log(A + sqrt(A*A + s)).
    float diff2 = fmaf(-b.x, dot, nc2 + b.y);            // |c - s*p|^2
    float z = fmaf(b.z * diff2, inv_omn, 1.0f);          // arcosh arg
    float x = temp * inv_omn;                            // asinh arg
    float A   = up ? fmaxf(z, 1.0f + 1e-7f) : fabsf(x);
    float sgn = up ? -1.0f : 1.0f;
    float val = __logf(A + sqrtf(fmaf(A, A, sgn)));
    return up ? val : copysignf(val, x) + 0.1f;          // +RADIUS
}

__global__ __launch_bounds__(256, 6)
void umbral_cone_kernel(const float* __restrict__ weight,
                        const int* __restrict__ inputs,
                        float* __restrict__ out,
                        int B) {
    __shared__ __align__(16) float4 s4[NROWS * RSTR];   // 36000 B
    __shared__ __align__(16) float4 srow[RPB * 2];      // per-row parent scalars

    const int tid  = threadIdx.x;
    const int row0 = blockIdx.x * RPB;
    const int g0   = tid >> 3;      // gathered-row id at u=0  (0..31)
    const int fi   = tid & 7;       // float4 lane within the 128B row
    const int gbase = row0 * KTOT;  // fits int32 (max 819200)
    const bool full = (row0 + RPB <= B);

    // ---------- Phase 1: index preload + cp.async gather ----------
    // 250 rows, 32 rows per sweep: u=0..6 full, u==7 only g0<26.
    if (full) {
        int idxv[8];
        #pragma unroll
        for (int u = 0; u < 8; u++) {
            int g = g0 + 32 * u;
            if (u < 7 || g0 < NROWS - 224)
                idxv[u] = inputs[gbase + g];
        }
        #pragma unroll
        for (int u = 0; u < 8; u++) {
            int g = g0 + 32 * u;
            if (u < 7 || g0 < NROWS - 224)
                cp16(&s4[g * RSTR + fi], (const float4*)(weight + idxv[u] * 32) + fi);
        }
    } else {
        const int lim = (B - row0) * KTOT;
        #pragma unroll
        for (int u = 0; u < 8; u++) {
            int g = g0 + 32 * u;
            if (g < lim && g < NROWS) {
                int idx = inputs[gbase + g];
                cp16(&s4[g * RSTR + fi], (const float4*)(weight + idx * 32) + fi);
            }
        }
    }
    asm volatile("cp.async.commit_group;\n");
    asm volatile("cp.async.wait_group 0;\n" ::: "memory");
    __syncthreads();

    // ---------- Phase 2a: per-row parent scalars (5 threads) ----------
    if (tid < RPB && (full || tid < B - row0)) {
        const float4* pb = &s4[(tid * KTOT) * RSTR];
        float np2 = 0.f;
        #pragma unroll
        for (int i = 0; i < 8; i++) {
            float4 v = pb[i];
            np2 = fmaf(v.x, v.x, fmaf(v.y, v.y, fmaf(v.z, v.z, fmaf(v.w, v.w, np2))));
        }
        float4 a, b;
        parent_scalars(np2, a, b);
        srow[tid * 2 + 0] = a;
        srow[tid * 2 + 1] = b;
    }
    __syncthreads();

    // ---------- Phase 2b: one thread per (row, child) pair ----------
    if (tid < RPB * NCH) {
        const int r = tid / NCH;
        const int j = tid - r * NCH;
        if (full || row0 + r < B) {
            const float4* pb = &s4[(r * KTOT) * RSTR];
            const float4* cb = &s4[(r * KTOT + 1 + j) * RSTR];

            float nc2 = 0.f, dot = 0.f;
            #pragma unroll
            for (int i = 0; i < 8; i++) {
                float4 pv = pb[i];   // broadcast within phase
                float4 cv = cb[i];   // stride-36 floats -> conflict-free
                nc2 = fmaf(cv.x, cv.x, nc2); nc2 = fmaf(cv.y, cv.y, nc2);
                nc2 = fmaf(cv.z, cv.z, nc2); nc2 = fmaf(cv.w, cv.w, nc2);
                dot = fmaf(pv.x, cv.x, dot); dot = fmaf(pv.y, cv.y, dot);
                dot = fmaf(pv.z, cv.z, dot); dot = fmaf(pv.w, cv.w, dot);
            }

            float dist = pair_tail(nc2, dot, srow[r * 2 + 0], srow[r * 2 + 1]);
            out[row0 * NCH + tid] = dist;     // (row0+r)*49 + j == row0*49 + tid
        }
    }
}

extern "C" void kernel_launch(void* const* d_in, const int* in_sizes, int n_in,
                              void* d_out, int out_size) {
    const float* weight = (const float*)d_in[0];
    const int*   inputs = (const int*)d_in[1];
    float*       out    = (float*)d_out;

    int B = in_sizes[1] / KTOT;          // 16384
    int grid = (B + RPB - 1) / RPB;      // 3277

    umbral_cone_kernel<<<grid, 256>>>(weight, inputs, out, B);
}